// round 9
// baseline (speedup 1.0000x reference)
#include <cuda_runtime.h>

#define NT  256   // prep threads
#define NTP 512   // pass threads

// 8 MB state, tables, composed unitaries — all __device__ globals (no allocs).
__device__ float2 g_psi[16 * 65536];
__device__ float2 g_U[240];       // 60 composed 2x2 unitaries
__device__ float2 g_d0[65536];    // layer0 ring phases, depth 0
__device__ float2 g_d1[65536];    // layer0 ring phases, depth 1
__device__ float2 g_t1[512];      // layer1 ring phases (2 depths x 256)
__device__ float2 g_t2[32];       // layer2 (2 x 16)
__device__ float2 g_t3[8];        // layer3 (2 x 4)

__device__ __forceinline__ float2 cmul(float2 a, float2 b) {
    return make_float2(fmaf(a.x, b.x, -a.y * b.y), fmaf(a.x, b.y, a.y * b.x));
}
__device__ __forceinline__ float2 cadd(float2 a, float2 b) {
    return make_float2(a.x + b.x, a.y + b.y);
}
__device__ __forceinline__ void mm2(const float2* A, const float2* B, float2* C) {
    C[0] = cadd(cmul(A[0], B[0]), cmul(A[1], B[2]));
    C[1] = cadd(cmul(A[0], B[1]), cmul(A[1], B[3]));
    C[2] = cadd(cmul(A[2], B[0]), cmul(A[3], B[2]));
    C[3] = cadd(cmul(A[2], B[1]), cmul(A[3], B[3]));
}

// Bank-conflict-killing swizzle: XOR low nibble with bits 4-7. Involution,
// makes all lane-stride patterns (1,2,4,8,16 float2s) exactly-2-phase.
__device__ __forceinline__ int SWZ(int i) { return i ^ ((i >> 4) & 15); }
// Insert a zero bit at position B.
__device__ __forceinline__ int insb(int x, int B) {
    return ((x >> B) << (B + 1)) | (x & ((1 << B) - 1));
}

struct PhOne {
    __device__ __forceinline__ float2 operator()(int) const { return make_float2(1.f, 0.f); }
};

// ---------------------------------------------------------------------------
// Prep: compose RX*RZ*RX unitaries, build all ring-phase tables, zero output.
// ---------------------------------------------------------------------------
__global__ __launch_bounds__(NT) void prep_kernel(
    const float* __restrict__ p0, const float* __restrict__ p1,
    const float* __restrict__ p2, const float* __restrict__ p3,
    float* __restrict__ out)
{
    int t = blockIdx.x * blockDim.x + threadIdx.x;   // 0..65535

    {
        float ph0 = 0.f, ph1 = 0.f;
        #pragma unroll
        for (int j = 0; j < 16; j++) {
            int jn = (j + 1) & 15;
            int x = ((t >> (15 - j)) ^ (t >> (15 - jn))) & 1;
            float sg = x ? 0.5f : -0.5f;
            ph0 += sg * p0[4 * j + 3];
            ph1 += sg * p0[4 * j + 67];
        }
        g_d0[t] = make_float2(cosf(ph0), sinf(ph0));
        g_d1[t] = make_float2(cosf(ph1), sinf(ph1));
    }

    if (t < 60) {
        const float* pp; int base;
        if (t < 32)      { pp = p0; int d = t >> 4;        int s = t & 15;       base = 4 * s + 64 * d; }
        else if (t < 48) { pp = p1; int d = (t - 32) >> 3; int s = (t - 32) & 7; base = 4 * s + 32 * d; }
        else if (t < 56) { pp = p2; int d = (t - 48) >> 2; int s = (t - 48) & 3; base = 4 * s + 16 * d; }
        else             { pp = p3; int d = (t - 56) >> 1; int s = (t - 56) & 1; base = 4 * s + 8 * d; }
        float a = pp[base] * 0.5f, b = pp[base + 1] * 0.5f, c = pp[base + 2] * 0.5f;
        float ca = cosf(a), sa = sinf(a);
        float cb = cosf(b), sb = sinf(b);
        float cc = cosf(c), sc = sinf(c);
        float2 RXa[4] = { {ca,0.f}, {0.f,-sa}, {0.f,-sa}, {ca,0.f} };
        float2 RZb[4] = { {cb,-sb}, {0.f,0.f}, {0.f,0.f}, {cb,sb} };
        float2 RXc[4] = { {cc,0.f}, {0.f,-sc}, {0.f,-sc}, {cc,0.f} };
        float2 M[4], U[4];
        mm2(RZb, RXa, M);
        mm2(RXc, M, U);
        g_U[t * 4 + 0] = U[0]; g_U[t * 4 + 1] = U[1];
        g_U[t * 4 + 2] = U[2]; g_U[t * 4 + 3] = U[3];
    }

    if (t < 512) {
        int d = t >> 8, idx = t & 255;
        float ph = 0.f;
        #pragma unroll
        for (int j = 0; j < 8; j++) {
            int jn = (j + 1) & 7;
            int x = ((idx >> (7 - j)) ^ (idx >> (7 - jn))) & 1;
            ph += (x ? 0.5f : -0.5f) * p1[4 * j + 3 + 32 * d];
        }
        g_t1[t] = make_float2(cosf(ph), sinf(ph));
    }

    if (t < 32) {
        int d = t >> 4, idx = t & 15;
        float ph = 0.f;
        #pragma unroll
        for (int j = 0; j < 4; j++) {
            int jn = (j + 1) & 3;
            int x = ((idx >> (3 - j)) ^ (idx >> (3 - jn))) & 1;
            ph += (x ? 0.5f : -0.5f) * p2[4 * j + 3 + 16 * d];
        }
        g_t2[t] = make_float2(cosf(ph), sinf(ph));
    }

    if (t < 8) {
        int d = t >> 2, idx = t & 3;
        int x = ((idx >> 1) ^ idx) & 1;
        float sg = x ? 0.5f : -0.5f;
        float ph = sg * (p3[3 + 8 * d] + p3[7 + 8 * d]);
        g_t3[t] = make_float2(cosf(ph), sinf(ph));
    }

    if (t < 16) out[t] = 0.f;
}

// ---------------------------------------------------------------------------
// 3-gate cell sweep: gates u2/u1/u0 on local bits Q2>Q1>Q0. 512 cells of 8
// amps, one cell per thread, single iteration, one barrier. Phase functor is
// applied at load time (logical index).
// ---------------------------------------------------------------------------
template<int Q2, int Q1, int Q0, class PHF>
__device__ __forceinline__ void csweep3_ph(float2* s, int u2, int u1, int u0, PHF ph) {
    const float2 A0 = g_U[4*u0], A1 = g_U[4*u0+1], A2 = g_U[4*u0+2], A3 = g_U[4*u0+3];
    const float2 Bg0 = g_U[4*u1], Bg1 = g_U[4*u1+1], Bg2 = g_U[4*u1+2], Bg3 = g_U[4*u1+3];
    const float2 C0 = g_U[4*u2], C1 = g_U[4*u2+1], C2 = g_U[4*u2+2], C3 = g_U[4*u2+3];
    int c = threadIdx.x;
    int base = insb(insb(insb(c, Q0), Q1), Q2);
    float2 a[8];
    #pragma unroll
    for (int b = 0; b < 8; b++) {
        int idx = base | ((b >> 2) << Q2) | (((b >> 1) & 1) << Q1) | ((b & 1) << Q0);
        a[b] = cmul(s[SWZ(idx)], ph(idx));
    }
    #pragma unroll
    for (int p = 0; p < 4; p++) {              // gate on Q0: (0,1)(2,3)(4,5)(6,7)
        float2 x = a[2*p], y = a[2*p+1];
        a[2*p]   = cadd(cmul(A0, x), cmul(A1, y));
        a[2*p+1] = cadd(cmul(A2, x), cmul(A3, y));
    }
    #pragma unroll
    for (int p = 0; p < 4; p++) {              // gate on Q1: (0,2)(1,3)(4,6)(5,7)
        int lo = (p & 1) | ((p >> 1) << 2);
        float2 x = a[lo], y = a[lo + 2];
        a[lo]     = cadd(cmul(Bg0, x), cmul(Bg1, y));
        a[lo + 2] = cadd(cmul(Bg2, x), cmul(Bg3, y));
    }
    #pragma unroll
    for (int p = 0; p < 4; p++) {              // gate on Q2: (b, b+4)
        float2 x = a[p], y = a[p + 4];
        a[p]     = cadd(cmul(C0, x), cmul(C1, y));
        a[p + 4] = cadd(cmul(C2, x), cmul(C3, y));
    }
    #pragma unroll
    for (int b = 0; b < 8; b++) {
        int idx = base | ((b >> 2) << Q2) | (((b >> 1) & 1) << Q1) | ((b & 1) << Q0);
        s[SWZ(idx)] = a[b];
    }
    __syncthreads();
}
template<int Q2, int Q1, int Q0>
__device__ __forceinline__ void csweep3(float2* s, int u2, int u1, int u0) {
    csweep3_ph<Q2, Q1, Q0>(s, u2, u1, u0, PhOne());
}

// ---------------------------------------------------------------------------
// 2-gate cell sweep (kept for pairs that don't form triples).
// ---------------------------------------------------------------------------
template<int BH, int BL, class PHF>
__device__ __forceinline__ void csweep_ph(float2* s, int uh, int ul, PHF ph) {
    const float2 H0 = g_U[4*uh], H1 = g_U[4*uh+1], H2 = g_U[4*uh+2], H3 = g_U[4*uh+3];
    const float2 L0 = g_U[4*ul], L1 = g_U[4*ul+1], L2 = g_U[4*ul+2], L3 = g_U[4*ul+3];
    #pragma unroll
    for (int it = 0; it < 2; it++) {
        int c = threadIdx.x + it * NTP;
        int base = insb(insb(c, BL), BH);
        int i01 = base | (1 << BL);
        int i10 = base | (1 << BH);
        int i11 = i10 | (1 << BL);
        float2 a00 = cmul(s[SWZ(base)], ph(base));
        float2 a01 = cmul(s[SWZ(i01)],  ph(i01));
        float2 a10 = cmul(s[SWZ(i10)],  ph(i10));
        float2 a11 = cmul(s[SWZ(i11)],  ph(i11));
        float2 b00 = cadd(cmul(L0, a00), cmul(L1, a01));
        float2 b10 = cadd(cmul(L0, a10), cmul(L1, a11));
        s[SWZ(base)] = cadd(cmul(H0, b00), cmul(H1, b10));
        s[SWZ(i10)]  = cadd(cmul(H2, b00), cmul(H3, b10));
        float2 b01 = cadd(cmul(L2, a00), cmul(L3, a01));
        float2 b11 = cadd(cmul(L2, a10), cmul(L3, a11));
        s[SWZ(i01)]  = cadd(cmul(H0, b01), cmul(H1, b11));
        s[SWZ(i11)]  = cadd(cmul(H2, b01), cmul(H3, b11));
    }
    __syncthreads();
}
template<int BH, int BL>
__device__ __forceinline__ void csweep(float2* s, int uh, int ul) {
    csweep_ph<BH, BL>(s, uh, ul, PhOne());
}

// ---------------------------------------------------------------------------
// Fused diagonal + CNOT-layer permutation (XOR involution). new[l]=old[p]*ph(p).
// ---------------------------------------------------------------------------
template<class FXF, class PHF>
__device__ __forceinline__ void perm_ph(float2* s, FXF fx, PHF ph) {
    #pragma unroll
    for (int i = 0; i < 8; i++) {
        int l = threadIdx.x + i * NTP;
        int f = fx(l);
        int p = l ^ f;
        if (f == 0) {
            s[SWZ(l)] = cmul(s[SWZ(l)], ph(l));
        } else if (l < p) {
            float2 a = s[SWZ(l)], b = s[SWZ(p)];
            s[SWZ(l)] = cmul(b, ph(p));
            s[SWZ(p)] = cmul(a, ph(l));
        }
    }
    __syncthreads();
}

// ---------------------------------------------------------------------------
// Pass 1: local = amp bits 0..11 (wires 4..15). Layer0 d0 on wires 4..15.
// Local bit b holds wire 15-b -> U(15-b).
// ---------------------------------------------------------------------------
__global__ __launch_bounds__(NTP, 2) void pass1_kernel(
    const float* __restrict__ xre, const float* __restrict__ xim)
{
    __shared__ float2 s[4096];
    int b = blockIdx.x >> 4, tile = blockIdx.x & 15;
    int base = (b << 16) | (tile << 12);
    #pragma unroll
    for (int i = 0; i < 8; i++) {
        int l = threadIdx.x + i * NTP;
        s[SWZ(l)] = make_float2(xre[base + l], xim[base + l]);
    }
    __syncthreads();
    csweep3<11, 10, 9>(s, 4, 5, 6);
    csweep3<8, 7, 6>(s, 7, 8, 9);
    csweep3<5, 4, 3>(s, 10, 11, 12);
    csweep3<2, 1, 0>(s, 13, 14, 15);
    #pragma unroll
    for (int i = 0; i < 8; i++) {
        int l = threadIdx.x + i * NTP;
        g_psi[base + l] = s[SWZ(l)];
    }
}

// ---------------------------------------------------------------------------
// Pass 2: local amp bits {0-4,7,9,11,12-15}. d0 on wires 0-3; diag D0; d1 on
// 12 local wires. Global amp bits {5,6,8,10}.
// Local->U map (d1): l11..l8 -> 16..19, l7->20(w4), l6->22(w6), l5->24(w8),
// l4->27(w11), l3..l0 -> 28..31.
// ---------------------------------------------------------------------------
__device__ __forceinline__ int expand2x(int l) {
    return (l & 0x1F) | ((l & 0x20) << 2) | ((l & 0x40) << 3) | ((l & 0xF80) << 4);
}
__global__ __launch_bounds__(NTP, 2) void pass2_kernel() {
    __shared__ float2 s[4096];
    int b = blockIdx.x >> 4, tile = blockIdx.x & 15;
    unsigned tor = ((tile & 3) << 5) | ((tile & 4) << 6) | ((tile & 8) << 7);
    unsigned gb = (unsigned)b << 16;
    #pragma unroll
    for (int i = 0; i < 8; i++) {
        int l = threadIdx.x + i * NTP;
        s[SWZ(l)] = g_psi[gb | tor | expand2x(l)];
    }
    __syncthreads();
    // layer0 d0 on wires 0..3 (locals 11,10,9,8)
    csweep<11, 8>(s, 0, 3);
    csweep<10, 9>(s, 1, 2);
    // layer0 d1, ring diag D0 folded into the first sweep's load
    csweep3_ph<11, 10, 9>(s, 16, 17, 18, [&](int l) { return g_d0[tor | expand2x(l)]; });
    csweep3<8, 7, 6>(s, 19, 20, 22);
    csweep3<5, 4, 3>(s, 24, 27, 28);
    csweep3<2, 1, 0>(s, 29, 30, 31);
    #pragma unroll
    for (int i = 0; i < 8; i++) {
        int l = threadIdx.x + i * NTP;
        g_psi[gb | tor | expand2x(l)] = s[SWZ(l)];
    }
}

// ---------------------------------------------------------------------------
// Pass 3: local amp bits {0-6,8,10,12,14,15}. Global amp bits {7,9,11,13}.
// Local map: l11=w0 l10=w1 l9=w3 l8=w5 l7=w7 l6=w9 l5=w10 l4..l0=w11..w15.
// ---------------------------------------------------------------------------
__device__ __forceinline__ int expand3x(int l) {
    return (l & 0x7F) | ((l & 0x80) << 1) | ((l & 0x100) << 2) |
           ((l & 0x200) << 3) | ((l & 0xC00) << 4);
}
__global__ __launch_bounds__(NTP, 2) void pass3_kernel() {
    __shared__ float2 s[4096];
    int b = blockIdx.x >> 4, tile = blockIdx.x & 15;
    unsigned tor = ((tile & 1) << 7) | ((tile & 2) << 8) | ((tile & 4) << 9) | ((tile & 8) << 10);
    unsigned gb = (unsigned)b << 16;
    #pragma unroll
    for (int i = 0; i < 8; i++) {
        int l = threadIdx.x + i * NTP;
        s[SWZ(l)] = g_psi[gb | tor | expand3x(l)];
    }
    __syncthreads();
    // layer0 d1 leftovers: w5->l8(U21), w7->l7(U23), w9->l6(U25), w10->l5(U26)
    csweep<8, 5>(s, 21, 26);
    csweep<7, 6>(s, 23, 25);
    // diag D1 + all 8 pool CNOTs fused (targets l10,l9,l8,l7,l6,l4,l2,l0).
    {
        int fc = (((tile >> 3) & 1) << 9) | (((tile >> 2) & 1) << 8) |
                 (((tile >> 1) & 1) << 7) | ((tile & 1) << 6);
        perm_ph(s,
            [&](int l) {
                return ((((l >> 11) & 1) << 10) | (((l >> 5) & 1) << 4) |
                        (((l >> 3) & 1) << 2) | ((l >> 1) & 1)) | fc;
            },
            [&](int l) { return g_d1[tor | expand3x(l)]; });
    }
    // layer1 d0 on wires 0,10,12,14 -> locals 11(U32),5(U37),3(U38),1(U39)
    csweep<11, 1>(s, 32, 39);
    csweep<5, 3>(s, 37, 38);
    #pragma unroll
    for (int i = 0; i < 8; i++) {
        int l = threadIdx.x + i * NTP;
        g_psi[gb | tor | expand3x(l)] = s[SWZ(l)];
    }
}

// ---------------------------------------------------------------------------
// Pass 4: local amp bits {0-7,9,11,13,15}. Global amp bits {8,10,12,14}.
// Local map: l11=w0 l10=w2 l9=w4 l8=w6 l7=w8 l5=w10 l3=w12 l1=w14.
// ---------------------------------------------------------------------------
__device__ __forceinline__ int expand4x(int l) {
    return (l & 0xFF) | ((l & 0x100) << 1) | ((l & 0x200) << 2) |
           ((l & 0x400) << 3) | ((l & 0x800) << 4);
}
__device__ __forceinline__ int p4_idx8(int l) {
    return ((l >> 4) & 0xF8) | ((l >> 3) & 4) | ((l >> 2) & 2) | ((l >> 1) & 1);
}
__device__ __forceinline__ int p4_idx4(int l) {
    return ((l >> 8) & 8) | ((l >> 7) & 4) | ((l >> 6) & 2) | ((l >> 3) & 1);
}
__device__ __forceinline__ int p4_idx2(int l) {
    return ((l >> 10) & 2) | ((l >> 7) & 1);
}
__global__ __launch_bounds__(NTP, 2) void pass4_kernel(float* __restrict__ out) {
    __shared__ float2 s[4096];
    __shared__ float ws[16];
    int b = blockIdx.x >> 4, tile = blockIdx.x & 15;
    unsigned tor = ((tile & 1) << 8) | ((tile & 2) << 9) | ((tile & 4) << 10) | ((tile & 8) << 11);
    unsigned gb = (unsigned)b << 16;
    #pragma unroll
    for (int i = 0; i < 8; i++) {
        int l = threadIdx.x + i * NTP;
        s[SWZ(l)] = g_psi[gb | tor | expand4x(l)];
    }
    __syncthreads();

    // layer1 d0 leftovers: w2->l10(U33), w4->l9(U34), w6->l8(U35), w8->l7(U36)
    csweep<10, 7>(s, 33, 36);
    csweep<9, 8>(s, 34, 35);
    // layer1 d1 (8 gates) with diag D0 folded into the first sweep
    csweep3_ph<11, 10, 9>(s, 40, 41, 42, [&](int l) { return g_t1[p4_idx8(l)]; });
    csweep3<8, 7, 5>(s, 43, 44, 45);
    csweep<3, 1>(s, 46, 47);
    // diag D1 + layer1 pool (l10<-l11, l8<-l9, l5<-l7, l1<-l3)
    perm_ph(s,
        [&](int l) {
            return (((l >> 11) & 1) << 10) | (((l >> 9) & 1) << 8) |
                   (((l >> 7) & 1) << 5) | (((l >> 3) & 1) << 1);
        },
        [&](int l) { return g_t1[256 + p4_idx8(l)]; });

    // layer2 d0: w0->l11(U48), w4->l9(U49), w8->l7(U50), w12->l3(U51)
    csweep<11, 3>(s, 48, 51);
    csweep<9, 7>(s, 49, 50);
    // layer2 d1 with diag D0 folded
    csweep_ph<11, 3>(s, 52, 55, [&](int l) { return g_t2[p4_idx4(l)]; });
    csweep<9, 7>(s, 53, 54);
    // diag D1 + layer2 pool (l9<-l11, l3<-l7)
    perm_ph(s,
        [&](int l) {
            return (((l >> 11) & 1) << 9) | (((l >> 7) & 1) << 3);
        },
        [&](int l) { return g_t2[16 + p4_idx4(l)]; });

    // layer3 d0: w0->l11(U56), w8->l7(U57)
    csweep<11, 7>(s, 56, 57);
    // layer3 d1 with diag D0 folded
    csweep_ph<11, 7>(s, 58, 59, [&](int l) { return g_t3[p4_idx2(l)]; });
    // diag D1 + layer3 pool (l7<-l11)
    perm_ph(s,
        [&](int l) { return ((l >> 11) & 1) << 7; },
        [&](int l) { return g_t3[4 + p4_idx2(l)]; });

    // measure Z on wire 0 (local bit 11)
    float acc = 0.f;
    #pragma unroll
    for (int i = 0; i < 8; i++) {
        int l = threadIdx.x + i * NTP;
        float2 a = s[SWZ(l)];
        float p = fmaf(a.x, a.x, a.y * a.y);
        acc += ((l >> 11) & 1) ? -p : p;
    }
    #pragma unroll
    for (int o = 16; o > 0; o >>= 1) acc += __shfl_xor_sync(0xFFFFFFFFu, acc, o);
    if ((threadIdx.x & 31) == 0) ws[threadIdx.x >> 5] = acc;
    __syncthreads();
    if (threadIdx.x == 0) {
        float t = 0.f;
        #pragma unroll
        for (int k = 0; k < 16; k++) t += ws[k];
        atomicAdd(&out[b], t);
    }
}

// ---------------------------------------------------------------------------
extern "C" void kernel_launch(void* const* d_in, const int* in_sizes, int n_in,
                              void* d_out, int out_size) {
    const float* xre = (const float*)d_in[0];
    const float* xim = (const float*)d_in[1];
    const float* p0  = (const float*)d_in[2];
    const float* p1  = (const float*)d_in[3];
    const float* p2  = (const float*)d_in[4];
    const float* p3  = (const float*)d_in[5];
    float* out = (float*)d_out;

    prep_kernel<<<256, NT>>>(p0, p1, p2, p3, out);
    pass1_kernel<<<256, NTP>>>(xre, xim);
    pass2_kernel<<<256, NTP>>>();
    pass3_kernel<<<256, NTP>>>();
    pass4_kernel<<<256, NTP>>>(out);
}